// round 1
// baseline (speedup 1.0000x reference)
#include <cuda_runtime.h>
#include <cstdint>

// Problem dims
constexpr int Bdim = 64;
constexpr int Nseq = 512;
constexpr int E    = 128;
constexpr int D    = 128;
constexpr int H    = 4;

// Scratch (allocation-free: __device__ globals)
__device__ float g_Q [(size_t)Bdim*H*Nseq*D];   // [B,H,N,D]
__device__ float g_KT[(size_t)Bdim*H*D*Nseq];   // [B,H,D,N]  (K transposed)
__device__ float g_V [(size_t)Bdim*H*Nseq*E];   // [B,H,N,E]
__device__ float g_S [(size_t)Bdim*H*Nseq*Nseq];// [B,H,N,N]
__device__ float g_A [(size_t)Bdim*Nseq*H*E];   // [B,N,H*E]
__device__ float g_H1[(size_t)Bdim*Nseq*E];     // [B,N,E]

// ---------------------------------------------------------------------------
// Shared GEMM core: C_tile[64x128] = A[64xK] * B[Kx128], fp32, BK=32.
// 256 threads as 16x16; each thread owns a 4x8 micro-tile.
// As: [64][36] (row-major, padded), Bs: [32][132].
// Caller passes sm with >= 6528 floats. Ends with __syncthreads() so sm can
// be reused as epilogue staging.
// ---------------------------------------------------------------------------
__device__ __forceinline__ void gemm_core(
    const float* __restrict__ Ag, int lda,   // Ag = &A[rowBase*lda]
    const float* __restrict__ Bg, int ldb,   // Bg = &B[colBase]
    int K, float* sm, float acc[4][8])
{
    float* As = sm;              // 64*36 = 2304
    float* Bs = sm + 64 * 36;    // 32*132 = 4224
    const int tid = threadIdx.x;
    const int tx = tid & 15, ty = tid >> 4;

    #pragma unroll
    for (int i = 0; i < 4; i++)
        #pragma unroll
        for (int j = 0; j < 8; j++) acc[i][j] = 0.f;

    for (int kc = 0; kc < K; kc += 32) {
        // Load A tile: 64 rows x 32 k  (512 float4 slots, 2/thread)
        #pragma unroll
        for (int s = 0; s < 2; s++) {
            int slot = tid + s * 256;
            int r = slot >> 3, kseg = slot & 7;
            float4 v = *reinterpret_cast<const float4*>(Ag + (size_t)r * lda + kc + kseg * 4);
            *reinterpret_cast<float4*>(As + r * 36 + kseg * 4) = v;
        }
        // Load B tile: 32 k x 128 n  (1024 float4 slots, 4/thread)
        #pragma unroll
        for (int s = 0; s < 4; s++) {
            int slot = tid + s * 256;
            int kk = slot >> 5, nseg = slot & 31;
            float4 v = *reinterpret_cast<const float4*>(Bg + (size_t)(kc + kk) * ldb + nseg * 4);
            *reinterpret_cast<float4*>(Bs + kk * 132 + nseg * 4) = v;
        }
        __syncthreads();
        #pragma unroll
        for (int k = 0; k < 32; k++) {
            float a0 = As[(ty * 4 + 0) * 36 + k];
            float a1 = As[(ty * 4 + 1) * 36 + k];
            float a2 = As[(ty * 4 + 2) * 36 + k];
            float a3 = As[(ty * 4 + 3) * 36 + k];
            float4 b0 = *reinterpret_cast<const float4*>(Bs + k * 132 + tx * 8);
            float4 b1 = *reinterpret_cast<const float4*>(Bs + k * 132 + tx * 8 + 4);
            float bb[8] = {b0.x, b0.y, b0.z, b0.w, b1.x, b1.y, b1.z, b1.w};
            float aa[4] = {a0, a1, a2, a3};
            #pragma unroll
            for (int i = 0; i < 4; i++)
                #pragma unroll
                for (int j = 0; j < 8; j++)
                    acc[i][j] += aa[i] * bb[j];
        }
        __syncthreads();   // protects next-iter loads AND epilogue smem reuse
    }
}

// Direct coalesced store of the 4x8 micro-tiles.
__device__ __forceinline__ void epi_store_direct(float acc[4][8], float* __restrict__ Cg, int ldc)
{
    const int tx = threadIdx.x & 15, ty = threadIdx.x >> 4;
    #pragma unroll
    for (int i = 0; i < 4; i++) {
        float4 v0 = make_float4(acc[i][0], acc[i][1], acc[i][2], acc[i][3]);
        float4 v1 = make_float4(acc[i][4], acc[i][5], acc[i][6], acc[i][7]);
        float* p = Cg + (size_t)(ty * 4 + i) * ldc + tx * 8;
        *reinterpret_cast<float4*>(p)     = v0;
        *reinterpret_cast<float4*>(p + 4) = v1;
    }
}

// Row-wise LN stats over a [64][132-strided] staged tile with 128 valid cols.
// 4 threads per row; rotated column access to avoid bank conflicts.
__device__ __forceinline__ void ln_stats(const float* __restrict__ Cs,
                                         float* __restrict__ smean,
                                         float* __restrict__ srstd)
{
    const int t = threadIdx.x;
    const int row = t >> 2, part = t & 3;
    float s = 0.f, s2 = 0.f;
    #pragma unroll
    for (int q = 0; q < 32; q++) {
        int col = part * 32 + ((q + part * 8) & 31);
        float v = Cs[row * 132 + col];
        s += v; s2 += v * v;
    }
    s  += __shfl_xor_sync(0xffffffffu, s, 1);
    s  += __shfl_xor_sync(0xffffffffu, s, 2);
    s2 += __shfl_xor_sync(0xffffffffu, s2, 1);
    s2 += __shfl_xor_sync(0xffffffffu, s2, 2);
    if (part == 0) {
        float mean = s * (1.0f / 128.0f);
        float var  = s2 * (1.0f / 128.0f) - mean * mean;
        smean[row] = mean;
        srstd[row] = rsqrtf(var + 1e-5f);
    }
}

// ---------------------------------------------------------------------------
// Kernel 1: fused QKV projection + bias + LayerNorm (no affine).
// blockIdx = (rowTile of B*N, head, which{0:Q,1:K->transposed,2:V})
// ---------------------------------------------------------------------------
__global__ __launch_bounds__(256) void qkv_kernel(
    const float* __restrict__ x,
    const float* __restrict__ Wq, const float* __restrict__ bq,
    const float* __restrict__ Wk, const float* __restrict__ bk,
    const float* __restrict__ Wv, const float* __restrict__ bv)
{
    __shared__ float sm[8576];   // staging 64*132 + 64 mean + 64 rstd
    const int rowBase = blockIdx.x * 64;
    const int h = blockIdx.y;
    const int which = blockIdx.z;

    const float* W; const float* bias;
    if      (which == 0) { W = Wq + (size_t)h * E * D; bias = bq + h * D; }
    else if (which == 1) { W = Wk + (size_t)h * E * D; bias = bk + h * D; }
    else                 { W = Wv + (size_t)h * E * E; bias = bv + h * E; }

    float acc[4][8];
    gemm_core(x + (size_t)rowBase * E, E, W, D, E, sm, acc);

    const int tid = threadIdx.x, tx = tid & 15, ty = tid >> 4;
    float* Cs    = sm;
    float* smean = sm + 64 * 132;
    float* srstd = smean + 64;

    #pragma unroll
    for (int i = 0; i < 4; i++)
        #pragma unroll
        for (int j = 0; j < 8; j++)
            Cs[(ty * 4 + i) * 132 + tx * 8 + j] = acc[i][j] + bias[tx * 8 + j];
    __syncthreads();
    ln_stats(Cs, smean, srstd);
    __syncthreads();

    const int b = rowBase >> 9;        // rowBase / 512
    const int nBase = rowBase & 511;
    const int bh = b * H + h;

    if (which == 1) {
        // transposed store: g_KT[bh][d][n]
        float* outp = g_KT + (size_t)bh * D * Nseq;
        const int nl = tid & 63;
        const int d0 = (tid >> 6) * 32;
        const float mu = smean[nl], rs = srstd[nl];
        #pragma unroll
        for (int dd = 0; dd < 32; dd++) {
            int d = d0 + dd;
            outp[(size_t)d * Nseq + nBase + nl] = (Cs[nl * 132 + d] - mu) * rs;
        }
    } else {
        float* outp = (which == 0 ? g_Q : g_V) + ((size_t)bh * Nseq + nBase) * D;
        #pragma unroll
        for (int s = 0; s < 8; s++) {
            int idx4 = tid + s * 256;          // 2048 float4 slots
            int row = idx4 >> 5, c = (idx4 & 31) * 4;
            float mu = smean[row], rs = srstd[row];
            float4 v = *reinterpret_cast<const float4*>(Cs + row * 132 + c);
            v.x = (v.x - mu) * rs; v.y = (v.y - mu) * rs;
            v.z = (v.z - mu) * rs; v.w = (v.w - mu) * rs;
            *reinterpret_cast<float4*>(outp + (size_t)row * D + c) = v;
        }
    }
}

// ---------------------------------------------------------------------------
// Kernel 2: scores = Q @ K^T  (unscaled; scale fused into softmax)
// grid (8 mTiles, 4 nTiles, 256 bh)
// ---------------------------------------------------------------------------
__global__ __launch_bounds__(256) void scores_kernel()
{
    __shared__ float sm[6528];
    const int bh = blockIdx.z;
    const int rowBase = blockIdx.x * 64, colBase = blockIdx.y * 128;
    float acc[4][8];
    gemm_core(g_Q  + (size_t)bh * Nseq * D + (size_t)rowBase * D, D,
              g_KT + (size_t)bh * D * Nseq + colBase,             Nseq,
              D, sm, acc);
    epi_store_direct(acc,
        g_S + (size_t)bh * Nseq * Nseq + (size_t)rowBase * Nseq + colBase, Nseq);
}

// ---------------------------------------------------------------------------
// Kernel 3: softmax over the BATCH axis (b = 0..63), with /11 scale.
// One thread per (h,n,m); all 64 batch values kept in registers.
// ---------------------------------------------------------------------------
__global__ __launch_bounds__(256) void softmax_kernel()
{
    const size_t idx = (size_t)blockIdx.x * 256 + threadIdx.x;  // over H*N*N = 1M
    const size_t stride = (size_t)H * Nseq * Nseq;
    float v[64];
    float mx = -1e30f;
    #pragma unroll
    for (int b = 0; b < 64; b++) {
        float t = g_S[(size_t)b * stride + idx] * (1.0f / 11.0f);
        v[b] = t;
        mx = fmaxf(mx, t);
    }
    float s = 0.f;
    #pragma unroll
    for (int b = 0; b < 64; b++) {
        float e = __expf(v[b] - mx);
        v[b] = e;
        s += e;
    }
    const float inv = 1.0f / s;
    #pragma unroll
    for (int b = 0; b < 64; b++)
        g_S[(size_t)b * stride + idx] = v[b] * inv;
}

// ---------------------------------------------------------------------------
// Kernel 4: A = P @ V, written directly into concat layout [B,N,H*E]
// grid (8 nTiles, 1, 256 bh)
// ---------------------------------------------------------------------------
__global__ __launch_bounds__(256) void av_kernel()
{
    __shared__ float sm[6528];
    const int bh = blockIdx.z, b = bh >> 2, h = bh & 3;
    const int rowBase = blockIdx.x * 64;
    float acc[4][8];
    gemm_core(g_S + (size_t)bh * Nseq * Nseq + (size_t)rowBase * Nseq, Nseq,
              g_V + (size_t)bh * Nseq * E,                             E,
              Nseq, sm, acc);
    epi_store_direct(acc,
        g_A + ((size_t)b * Nseq + rowBase) * (H * E) + (size_t)h * E, H * E);
}

// ---------------------------------------------------------------------------
// Kernel 5: h1 = relu(A_cat @ W1 + b1)     [32768,512]@[512,128]
// ---------------------------------------------------------------------------
__global__ __launch_bounds__(256) void mlp1_kernel(
    const float* __restrict__ W1, const float* __restrict__ b1)
{
    __shared__ float sm[6528];
    const int rowBase = blockIdx.x * 64;
    float acc[4][8];
    gemm_core(g_A + (size_t)rowBase * (H * E), H * E, W1, E, H * E, sm, acc);
    const int tx = threadIdx.x & 15;
    #pragma unroll
    for (int i = 0; i < 4; i++)
        #pragma unroll
        for (int j = 0; j < 8; j++)
            acc[i][j] = fmaxf(acc[i][j] + b1[tx * 8 + j], 0.f);
    epi_store_direct(acc, g_H1 + (size_t)rowBase * E, E);
}

// ---------------------------------------------------------------------------
// Kernel 6: out = LN(x + relu(h1 @ W2 + b2)) * gamma + beta
// ---------------------------------------------------------------------------
__global__ __launch_bounds__(256) void mlp2_kernel(
    const float* __restrict__ x,
    const float* __restrict__ W2, const float* __restrict__ b2,
    const float* __restrict__ gamma, const float* __restrict__ beta,
    float* __restrict__ out)
{
    __shared__ float sm[8576];
    const int rowBase = blockIdx.x * 64;
    float acc[4][8];
    gemm_core(g_H1 + (size_t)rowBase * E, E, W2, E, E, sm, acc);

    const int tid = threadIdx.x, tx = tid & 15, ty = tid >> 4;
    float* Cs    = sm;
    float* smean = sm + 64 * 132;
    float* srstd = smean + 64;

    #pragma unroll
    for (int i = 0; i < 4; i++) {
        int rg = rowBase + ty * 4 + i;
        #pragma unroll
        for (int j = 0; j < 8; j++) {
            int col = tx * 8 + j;
            float m = fmaxf(acc[i][j] + b2[col], 0.f) + x[(size_t)rg * E + col];
            Cs[(ty * 4 + i) * 132 + col] = m;
        }
    }
    __syncthreads();
    ln_stats(Cs, smean, srstd);
    __syncthreads();

    #pragma unroll
    for (int s = 0; s < 8; s++) {
        int idx4 = tid + s * 256;
        int row = idx4 >> 5, c = (idx4 & 31) * 4;
        float mu = smean[row], rs = srstd[row];
        float4 v  = *reinterpret_cast<const float4*>(Cs + row * 132 + c);
        float4 g  = *reinterpret_cast<const float4*>(gamma + c);
        float4 be = *reinterpret_cast<const float4*>(beta + c);
        v.x = (v.x - mu) * rs * g.x + be.x;
        v.y = (v.y - mu) * rs * g.y + be.y;
        v.z = (v.z - mu) * rs * g.z + be.z;
        v.w = (v.w - mu) * rs * g.w + be.w;
        *reinterpret_cast<float4*>(out + (size_t)(rowBase + row) * E + c) = v;
    }
}

// ---------------------------------------------------------------------------
extern "C" void kernel_launch(void* const* d_in, const int* in_sizes, int n_in,
                              void* d_out, int out_size)
{
    const float* x     = (const float*)d_in[0];
    const float* Wq    = (const float*)d_in[1];
    const float* bq    = (const float*)d_in[2];
    const float* Wk    = (const float*)d_in[3];
    const float* bk    = (const float*)d_in[4];
    const float* Wv    = (const float*)d_in[5];
    const float* bv    = (const float*)d_in[6];
    const float* W1    = (const float*)d_in[7];
    const float* b1    = (const float*)d_in[8];
    const float* W2    = (const float*)d_in[9];
    const float* b2    = (const float*)d_in[10];
    const float* gamma = (const float*)d_in[11];
    const float* beta  = (const float*)d_in[12];
    float* out = (float*)d_out;

    dim3 blk(256);
    qkv_kernel   <<<dim3(512, 4, 3), blk>>>(x, Wq, bq, Wk, bk, Wv, bv);
    scores_kernel<<<dim3(8, 4, 256), blk>>>();
    softmax_kernel<<<dim3(4096), blk>>>();
    av_kernel    <<<dim3(8, 1, 256), blk>>>();
    mlp1_kernel  <<<dim3(512), blk>>>(W1, b1);
    mlp2_kernel  <<<dim3(512), blk>>>(x, W2, b2, gamma, beta, out);
}

// round 2
// speedup vs baseline: 1.7259x; 1.7259x over previous
#include <cuda_runtime.h>
#include <cstdint>

constexpr int Bdim = 64;
constexpr int Nseq = 512;
constexpr int E    = 128;
constexpr int D    = 128;
constexpr int H    = 4;

// Scratch (allocation-free: __device__ globals)
__device__ float g_Q [(size_t)Bdim*H*Nseq*D];   // [B*H][N][D]
__device__ float g_K [(size_t)Bdim*H*Nseq*D];   // [B*H][N][D]
__device__ float g_V [(size_t)Bdim*H*Nseq*E];   // [B*H][N][E]
__device__ float g_S [(size_t)Bdim*H*Nseq*Nseq];// [B][H][N][N]
__device__ float g_A [(size_t)Bdim*Nseq*H*E];   // [B,N,H*E]
__device__ float g_H1[(size_t)Bdim*Nseq*E];     // [B,N,E]

// ---------------------------------------------------------------------------
// 128x128 fp32 GEMM core. BK=8, double-buffered, 256 threads, 8x8 micro-tile.
// A is [M,K] row-major (staged transposed -> As[k][m]).
// B is [K,N] row-major normally; TRANSB: B is [N,K] row-major (both padded 132).
// smem layout (floats): As[2][8*132]=2112, Bs[2][8*132]=2112  => 4224 total.
// ---------------------------------------------------------------------------
#define TSTRIDE 132
#define BUFSZ   (8 * TSTRIDE)

template<bool TRANSB>
__device__ __forceinline__ void gemm128(
    const float* __restrict__ Ag, int lda,
    const float* __restrict__ Bg, int ldb,
    int K, float* __restrict__ sm, float acc[8][8])
{
    float* As = sm;               // 2 * BUFSZ
    float* Bs = sm + 2 * BUFSZ;   // 2 * BUFSZ

    const int tid  = threadIdx.x;
    const int lane = tid & 31, w = tid >> 5;
    const int wm = w >> 2, wn = w & 3;
    const int rc = lane >> 2, cc = lane & 3;
    const int mA0 = wm * 64 + rc * 4;
    const int nB0 = wn * 32 + cc * 4;

    // loader coords
    const int m_a = tid >> 1, k_a = (tid & 1) * 4;       // A: 128 x 8 tile
    const int k_b = tid >> 5, n_b = (tid & 31) * 4;      // B direct: 8 x 128
    const int n_t = tid >> 1, k_t = (tid & 1) * 4;       // B transposed: 128 x 8

    #pragma unroll
    for (int i = 0; i < 8; i++)
        #pragma unroll
        for (int j = 0; j < 8; j++) acc[i][j] = 0.f;

    const float* pA = Ag + (size_t)m_a * lda + k_a;
    const float* pB = TRANSB ? (Bg + (size_t)n_t * ldb + k_t)
                             : (Bg + (size_t)k_b * ldb + n_b);

    float4 aR = *reinterpret_cast<const float4*>(pA);
    float4 bR = *reinterpret_cast<const float4*>(pB);

    // stage tile 0
    {
        float av[4] = {aR.x, aR.y, aR.z, aR.w};
        #pragma unroll
        for (int t = 0; t < 4; t++) As[(k_a + t) * TSTRIDE + m_a] = av[t];
        if (TRANSB) {
            float bv[4] = {bR.x, bR.y, bR.z, bR.w};
            #pragma unroll
            for (int t = 0; t < 4; t++) Bs[(k_t + t) * TSTRIDE + n_t] = bv[t];
        } else {
            *reinterpret_cast<float4*>(Bs + k_b * TSTRIDE + n_b) = bR;
        }
    }
    __syncthreads();

    const int NT = K >> 3;
    for (int it = 0; it < NT; it++) {
        const int cur = (it & 1) * BUFSZ, nxt = ((it + 1) & 1) * BUFSZ;
        if (it + 1 < NT) {
            const int kc = (it + 1) * 8;
            aR = *reinterpret_cast<const float4*>(pA + kc);
            bR = TRANSB ? *reinterpret_cast<const float4*>(pB + kc)
                        : *reinterpret_cast<const float4*>(pB + (size_t)kc * ldb);
        }
        const float* Ac = As + cur;
        const float* Bc = Bs + cur;
        #pragma unroll
        for (int k = 0; k < 8; k++) {
            const float* ar = Ac + k * TSTRIDE;
            const float* br = Bc + k * TSTRIDE;
            float4 a0 = *reinterpret_cast<const float4*>(ar + mA0);
            float4 a1 = *reinterpret_cast<const float4*>(ar + mA0 + 32);
            float4 b0 = *reinterpret_cast<const float4*>(br + nB0);
            float4 b1 = *reinterpret_cast<const float4*>(br + nB0 + 16);
            float a[8] = {a0.x,a0.y,a0.z,a0.w,a1.x,a1.y,a1.z,a1.w};
            float b[8] = {b0.x,b0.y,b0.z,b0.w,b1.x,b1.y,b1.z,b1.w};
            #pragma unroll
            for (int i = 0; i < 8; i++)
                #pragma unroll
                for (int j = 0; j < 8; j++)
                    acc[i][j] += a[i] * b[j];
        }
        if (it + 1 < NT) {
            float av[4] = {aR.x, aR.y, aR.z, aR.w};
            #pragma unroll
            for (int t = 0; t < 4; t++) As[nxt + (k_a + t) * TSTRIDE + m_a] = av[t];
            if (TRANSB) {
                float bv[4] = {bR.x, bR.y, bR.z, bR.w};
                #pragma unroll
                for (int t = 0; t < 4; t++) Bs[nxt + (k_t + t) * TSTRIDE + n_t] = bv[t];
            } else {
                *reinterpret_cast<float4*>(Bs + nxt + k_b * TSTRIDE + n_b) = bR;
            }
        }
        __syncthreads();
    }
}

// row index of acc[i][*] within the 128-row tile
__device__ __forceinline__ int acc_row(int i) {
    const int lane = threadIdx.x & 31, w = threadIdx.x >> 5;
    return (w >> 2) * 64 + ((i < 4) ? 0 : 32) + (lane >> 2) * 4 + (i & 3);
}
__device__ __forceinline__ int acc_col0() {
    const int lane = threadIdx.x & 31, w = threadIdx.x >> 5;
    return (w & 3) * 32 + (lane & 3) * 4;   // cols c0..c0+3 and c0+16..c0+19
}

// In-register block LayerNorm over 128 cols (no affine). lnbuf >= 1280 floats.
__device__ __forceinline__ void ln_block(float acc[8][8], float* lnbuf)
{
    float* lnS = lnbuf;          // 512
    float* lnQ = lnbuf + 512;    // 512
    float* mrs = lnbuf + 1024;   // 256
    const int tid = threadIdx.x, lane = tid & 31, w = tid >> 5;
    const int wn = w & 3, cc = lane & 3;

    #pragma unroll
    for (int i = 0; i < 8; i++) {
        float s = 0.f, q = 0.f;
        #pragma unroll
        for (int j = 0; j < 8; j++) { float v = acc[i][j]; s += v; q += v * v; }
        s += __shfl_xor_sync(0xffffffffu, s, 1);
        s += __shfl_xor_sync(0xffffffffu, s, 2);
        q += __shfl_xor_sync(0xffffffffu, q, 1);
        q += __shfl_xor_sync(0xffffffffu, q, 2);
        if (cc == 0) {
            int row = acc_row(i);
            lnS[row * 4 + wn] = s;
            lnQ[row * 4 + wn] = q;
        }
    }
    __syncthreads();
    if (tid < 128) {
        float s = lnS[tid*4] + lnS[tid*4+1] + lnS[tid*4+2] + lnS[tid*4+3];
        float q = lnQ[tid*4] + lnQ[tid*4+1] + lnQ[tid*4+2] + lnQ[tid*4+3];
        float mean = s * (1.0f / 128.0f);
        float var  = q * (1.0f / 128.0f) - mean * mean;
        mrs[tid]       = mean;
        mrs[128 + tid] = rsqrtf(var + 1e-5f);
    }
    __syncthreads();
    #pragma unroll
    for (int i = 0; i < 8; i++) {
        int row = acc_row(i);
        float mu = mrs[row], rs = mrs[128 + row];
        #pragma unroll
        for (int j = 0; j < 8; j++) acc[i][j] = (acc[i][j] - mu) * rs;
    }
}

__device__ __forceinline__ void store_tile(const float acc[8][8],
                                           float* __restrict__ Cg, int ldc)
{
    const int c0 = acc_col0();
    #pragma unroll
    for (int i = 0; i < 8; i++) {
        int r = acc_row(i);
        float4 v0 = make_float4(acc[i][0], acc[i][1], acc[i][2], acc[i][3]);
        float4 v1 = make_float4(acc[i][4], acc[i][5], acc[i][6], acc[i][7]);
        float* p = Cg + (size_t)r * ldc + c0;
        *reinterpret_cast<float4*>(p)      = v0;
        *reinterpret_cast<float4*>(p + 16) = v1;
    }
}

// ---------------------------------------------------------------------------
// Kernel 1: QKV projection + bias + LN (no affine). grid (256, H, 3)
// ---------------------------------------------------------------------------
__global__ __launch_bounds__(256, 2) void qkv_kernel(
    const float* __restrict__ x,
    const float* __restrict__ Wq, const float* __restrict__ bq,
    const float* __restrict__ Wk, const float* __restrict__ bk,
    const float* __restrict__ Wv, const float* __restrict__ bv)
{
    __shared__ float sm[4 * BUFSZ + 1280];
    const int rowBase = blockIdx.x * 128;       // over B*N
    const int h = blockIdx.y, which = blockIdx.z;

    const float* W; const float* bias;
    if      (which == 0) { W = Wq + (size_t)h * E * D; bias = bq + h * D; }
    else if (which == 1) { W = Wk + (size_t)h * E * D; bias = bk + h * D; }
    else                 { W = Wv + (size_t)h * E * E; bias = bv + h * E; }

    float acc[8][8];
    gemm128<false>(x + (size_t)rowBase * E, E, W, D, E, sm, acc);

    const int c0 = acc_col0();
    float4 bb0 = *reinterpret_cast<const float4*>(bias + c0);
    float4 bb1 = *reinterpret_cast<const float4*>(bias + c0 + 16);
    float bv8[8] = {bb0.x,bb0.y,bb0.z,bb0.w,bb1.x,bb1.y,bb1.z,bb1.w};
    #pragma unroll
    for (int i = 0; i < 8; i++)
        #pragma unroll
        for (int j = 0; j < 8; j++) acc[i][j] += bv8[j];

    ln_block(acc, sm + 4 * BUFSZ);

    const int b = rowBase >> 9;
    const int nBase = rowBase & 511;
    const int bh = b * H + h;
    float* out = (which == 0 ? g_Q : (which == 1 ? g_K : g_V));
    store_tile(acc, out + ((size_t)bh * Nseq + nBase) * 128, 128);
}

// ---------------------------------------------------------------------------
// Kernel 2: scores = Q @ K^T. grid (4, 4, 256)
// ---------------------------------------------------------------------------
__global__ __launch_bounds__(256, 2) void scores_kernel()
{
    __shared__ float sm[4 * BUFSZ];
    const int bh = blockIdx.z;
    const int rowBase = blockIdx.x * 128, colBase = blockIdx.y * 128;
    float acc[8][8];
    gemm128<true>(g_Q + ((size_t)bh * Nseq + rowBase) * D, D,
                  g_K + ((size_t)bh * Nseq + colBase) * D, D,
                  D, sm, acc);
    store_tile(acc, g_S + (size_t)bh * Nseq * Nseq + (size_t)rowBase * Nseq + colBase,
               Nseq);
}

// ---------------------------------------------------------------------------
// Kernel 3: softmax over BATCH axis, with /11 scale baked in.
// ---------------------------------------------------------------------------
__global__ __launch_bounds__(256) void softmax_kernel()
{
    const size_t idx = (size_t)blockIdx.x * 256 + threadIdx.x;  // H*N*N = 1M
    const size_t stride = (size_t)H * Nseq * Nseq;
    float v[64];
    float mx = -1e30f;
    #pragma unroll
    for (int b = 0; b < 64; b++) {
        float t = g_S[(size_t)b * stride + idx] * (1.0f / 11.0f);
        v[b] = t;
        mx = fmaxf(mx, t);
    }
    float s = 0.f;
    #pragma unroll
    for (int b = 0; b < 64; b++) { float e = __expf(v[b] - mx); v[b] = e; s += e; }
    const float inv = 1.0f / s;
    #pragma unroll
    for (int b = 0; b < 64; b++)
        g_S[(size_t)b * stride + idx] = v[b] * inv;
}

// ---------------------------------------------------------------------------
// Kernel 4: A = P @ V into concat layout. grid (4, 1, 256)
// ---------------------------------------------------------------------------
__global__ __launch_bounds__(256, 2) void av_kernel()
{
    __shared__ float sm[4 * BUFSZ];
    const int bh = blockIdx.z, b = bh >> 2, h = bh & 3;
    const int rowBase = blockIdx.x * 128;
    float acc[8][8];
    gemm128<false>(g_S + (size_t)bh * Nseq * Nseq + (size_t)rowBase * Nseq, Nseq,
                   g_V + (size_t)bh * Nseq * E, E,
                   Nseq, sm, acc);
    store_tile(acc, g_A + ((size_t)b * Nseq + rowBase) * (H * E) + (size_t)h * E,
               H * E);
}

// ---------------------------------------------------------------------------
// Kernel 5: h1 = relu(A_cat @ W1 + b1). grid (256)
// ---------------------------------------------------------------------------
__global__ __launch_bounds__(256, 2) void mlp1_kernel(
    const float* __restrict__ W1, const float* __restrict__ b1)
{
    __shared__ float sm[4 * BUFSZ];
    const int rowBase = blockIdx.x * 128;
    float acc[8][8];
    gemm128<false>(g_A + (size_t)rowBase * (H * E), H * E, W1, E, H * E, sm, acc);
    const int c0 = acc_col0();
    float4 bb0 = *reinterpret_cast<const float4*>(b1 + c0);
    float4 bb1 = *reinterpret_cast<const float4*>(b1 + c0 + 16);
    float bv8[8] = {bb0.x,bb0.y,bb0.z,bb0.w,bb1.x,bb1.y,bb1.z,bb1.w};
    #pragma unroll
    for (int i = 0; i < 8; i++)
        #pragma unroll
        for (int j = 0; j < 8; j++) acc[i][j] = fmaxf(acc[i][j] + bv8[j], 0.f);
    store_tile(acc, g_H1 + (size_t)rowBase * E, E);
}

// ---------------------------------------------------------------------------
// Kernel 6: out = LN(x + relu(h1 @ W2 + b2)) * gamma + beta. grid (256)
// ---------------------------------------------------------------------------
__global__ __launch_bounds__(256, 2) void mlp2_kernel(
    const float* __restrict__ x,
    const float* __restrict__ W2, const float* __restrict__ b2,
    const float* __restrict__ gamma, const float* __restrict__ beta,
    float* __restrict__ out)
{
    __shared__ float sm[4 * BUFSZ + 1280];
    const int rowBase = blockIdx.x * 128;
    float acc[8][8];
    gemm128<false>(g_H1 + (size_t)rowBase * E, E, W2, E, E, sm, acc);

    const int c0 = acc_col0();
    float4 bb0 = *reinterpret_cast<const float4*>(b2 + c0);
    float4 bb1 = *reinterpret_cast<const float4*>(b2 + c0 + 16);
    float bv8[8] = {bb0.x,bb0.y,bb0.z,bb0.w,bb1.x,bb1.y,bb1.z,bb1.w};
    #pragma unroll
    for (int i = 0; i < 8; i++) {
        int rg = rowBase + acc_row(i);
        float4 x0 = *reinterpret_cast<const float4*>(x + (size_t)rg * E + c0);
        float4 x1 = *reinterpret_cast<const float4*>(x + (size_t)rg * E + c0 + 16);
        float xv[8] = {x0.x,x0.y,x0.z,x0.w,x1.x,x1.y,x1.z,x1.w};
        #pragma unroll
        for (int j = 0; j < 8; j++)
            acc[i][j] = fmaxf(acc[i][j] + bv8[j], 0.f) + xv[j];
    }

    ln_block(acc, sm + 4 * BUFSZ);

    float4 g0 = *reinterpret_cast<const float4*>(gamma + c0);
    float4 g1 = *reinterpret_cast<const float4*>(gamma + c0 + 16);
    float4 e0 = *reinterpret_cast<const float4*>(beta + c0);
    float4 e1 = *reinterpret_cast<const float4*>(beta + c0 + 16);
    float gv[8] = {g0.x,g0.y,g0.z,g0.w,g1.x,g1.y,g1.z,g1.w};
    float ev[8] = {e0.x,e0.y,e0.z,e0.w,e1.x,e1.y,e1.z,e1.w};
    #pragma unroll
    for (int i = 0; i < 8; i++)
        #pragma unroll
        for (int j = 0; j < 8; j++) acc[i][j] = acc[i][j] * gv[j] + ev[j];

    store_tile(acc, out + (size_t)rowBase * E, E);
}

// ---------------------------------------------------------------------------
extern "C" void kernel_launch(void* const* d_in, const int* in_sizes, int n_in,
                              void* d_out, int out_size)
{
    const float* x     = (const float*)d_in[0];
    const float* Wq    = (const float*)d_in[1];
    const float* bq    = (const float*)d_in[2];
    const float* Wk    = (const float*)d_in[3];
    const float* bk    = (const float*)d_in[4];
    const float* Wv    = (const float*)d_in[5];
    const float* bv    = (const float*)d_in[6];
    const float* W1    = (const float*)d_in[7];
    const float* b1    = (const float*)d_in[8];
    const float* W2    = (const float*)d_in[9];
    const float* b2    = (const float*)d_in[10];
    const float* gamma = (const float*)d_in[11];
    const float* beta  = (const float*)d_in[12];
    float* out = (float*)d_out;

    dim3 blk(256);
    qkv_kernel    <<<dim3(256, 4, 3), blk>>>(x, Wq, bq, Wk, bk, Wv, bv);
    scores_kernel <<<dim3(4, 4, 256), blk>>>();
    softmax_kernel<<<dim3(4096), blk>>>();
    av_kernel     <<<dim3(4, 1, 256), blk>>>();
    mlp1_kernel   <<<dim3(256), blk>>>(W1, b1);
    mlp2_kernel   <<<dim3(256), blk>>>(x, W2, b2, gamma, beta, out);
}

// round 4
// speedup vs baseline: 2.2716x; 1.3162x over previous
#include <cuda_runtime.h>
#include <cuda_bf16.h>
#include <cstdint>

constexpr int Bdim = 64;
constexpr int Nseq = 512;
constexpr int E    = 128;
constexpr int D    = 128;
constexpr int H    = 4;

// ---------------- scratch (allocation-free) ----------------
__device__ __nv_bfloat16 g_Qh[(size_t)Bdim*H*Nseq*D];
__device__ __nv_bfloat16 g_Ql[(size_t)Bdim*H*Nseq*D];
__device__ __nv_bfloat16 g_Kh[(size_t)Bdim*H*Nseq*D];
__device__ __nv_bfloat16 g_Kl[(size_t)Bdim*H*Nseq*D];
__device__ __nv_bfloat16 g_Vh[(size_t)Bdim*H*Nseq*E];   // [bh][n][e]
__device__ __nv_bfloat16 g_Vl[(size_t)Bdim*H*Nseq*E];
__device__ __nv_bfloat16 g_Vth[(size_t)Bdim*H*E*Nseq];  // [bh][e][n]
__device__ __nv_bfloat16 g_Vtl[(size_t)Bdim*H*E*Nseq];
__device__ float         g_S [(size_t)Bdim*H*Nseq*Nseq];// [b][h][n][m] fp32
__device__ __nv_bfloat16 g_Ph[(size_t)Bdim*H*Nseq*Nseq];
__device__ __nv_bfloat16 g_Pl[(size_t)Bdim*H*Nseq*Nseq];
__device__ float g_A [(size_t)Bdim*Nseq*H*E];            // [B,N,H*E] fp32
__device__ float g_H1[(size_t)Bdim*Nseq*E];

// ======================= mma.sync machinery =======================
__device__ __forceinline__ void ldsm_x4(uint32_t r[4], const void* p) {
    uint32_t addr = (uint32_t)__cvta_generic_to_shared(p);
    asm volatile("ldmatrix.sync.aligned.m8n8.x4.shared.b16 {%0,%1,%2,%3}, [%4];"
                 : "=r"(r[0]), "=r"(r[1]), "=r"(r[2]), "=r"(r[3]) : "r"(addr));
}
__device__ __forceinline__ void mma16816(float c[4], const uint32_t a[4], const uint32_t b[2]) {
    asm volatile("mma.sync.aligned.m16n8k16.row.col.f32.bf16.bf16.f32 "
                 "{%0,%1,%2,%3}, {%4,%5,%6,%7}, {%8,%9}, {%0,%1,%2,%3};"
                 : "+f"(c[0]), "+f"(c[1]), "+f"(c[2]), "+f"(c[3])
                 : "r"(a[0]), "r"(a[1]), "r"(a[2]), "r"(a[3]), "r"(b[0]), "r"(b[1]));
}

// smem plane: 128 rows x 32 bf16 (64B rows), 16B chunks XOR-swizzled.
__device__ __forceinline__ int sw_idx(int row, int seg) {
    return row * 32 + ((seg ^ ((row >> 1) & 3)) << 3);
}

// load one [128 x 32] bf16 chunk gmem -> swizzled smem plane
__device__ __forceinline__ void ld_plane(__nv_bfloat16* dst, const __nv_bfloat16* src,
                                         int ld, int kc, int tid)
{
    #pragma unroll
    for (int s = 0; s < 2; s++) {
        int idx = tid + s * 256;
        int row = idx >> 2, seg = idx & 3;
        uint4 v = *reinterpret_cast<const uint4*>(src + (size_t)row * ld + kc + seg * 8);
        *reinterpret_cast<uint4*>(dst + sw_idx(row, seg)) = v;
    }
}

__device__ __forceinline__ void load_a_frag(uint32_t a[4][4], const __nv_bfloat16* plane,
                                            int m0, int seg_base, int lane)
{
    const int r = lane & 15, half = lane >> 4;
    #pragma unroll
    for (int t = 0; t < 4; t++)
        ldsm_x4(a[t], plane + sw_idx(m0 + t * 16 + r, seg_base + half));
}
__device__ __forceinline__ void load_b_frag(uint32_t b[4][2], const __nv_bfloat16* plane,
                                            int n0, int seg_base, int lane)
{
    const int r = lane & 15, half = lane >> 4;
    #pragma unroll
    for (int p = 0; p < 2; p++) {
        uint32_t t[4];
        ldsm_x4(t, plane + sw_idx(n0 + p * 16 + r, seg_base + half));
        b[2*p][0]   = t[0];
        b[2*p+1][0] = t[1];
        b[2*p][1]   = t[2];
        b[2*p+1][1] = t[3];
    }
}
__device__ __forceinline__ void mma_all(float acc[4][4][4], const uint32_t a[4][4],
                                        const uint32_t b[4][2])
{
    #pragma unroll
    for (int mt = 0; mt < 4; mt++)
        #pragma unroll
        for (int nt = 0; nt < 4; nt++)
            mma16816(acc[mt][nt], a[mt], b[nt]);
}

// ---------------------------------------------------------------------------
// Split-bf16 (3-product) 128x128 GEMM tile on mma.sync.
// A: [128 rows x K] K-major (hi/lo). B: [128 rows x K] K-major (hi/lo).
// C[m][n] += sum_k (Ahi+Alo)[m][k] * (Bhi+Blo)[n][k]   (lo*lo dropped)
// ---------------------------------------------------------------------------
__device__ void mma_gemm(const __nv_bfloat16* __restrict__ Ah,
                         const __nv_bfloat16* __restrict__ Al, int lda,
                         const __nv_bfloat16* __restrict__ Bh,
                         const __nv_bfloat16* __restrict__ Bl, int ldb,
                         int K, float* __restrict__ Cout, int ldc)
{
    __shared__ __nv_bfloat16 sm[4][128 * 32];
    const int tid = threadIdx.x, lane = tid & 31, wid = tid >> 5;
    const int m0 = (wid >> 2) * 64, n0 = (wid & 3) * 32;

    float acc[4][4][4];
    #pragma unroll
    for (int mt = 0; mt < 4; mt++)
        #pragma unroll
        for (int nt = 0; nt < 4; nt++)
            #pragma unroll
            for (int q = 0; q < 4; q++) acc[mt][nt][q] = 0.f;

    for (int kc = 0; kc < K; kc += 32) {
        __syncthreads();
        ld_plane(sm[0], Ah, lda, kc, tid);
        ld_plane(sm[1], Al, lda, kc, tid);
        ld_plane(sm[2], Bh, ldb, kc, tid);
        ld_plane(sm[3], Bl, ldb, kc, tid);
        __syncthreads();
        #pragma unroll
        for (int ks = 0; ks < 2; ks++) {
            const int seg = ks * 2;
            uint32_t a[4][4];
            uint32_t b[4][2];
            load_b_frag(b, sm[2], n0, seg, lane);   // B hi
            load_a_frag(a, sm[0], m0, seg, lane);   // A hi
            mma_all(acc, a, b);                     // hi*hi
            load_a_frag(a, sm[1], m0, seg, lane);   // A lo
            mma_all(acc, a, b);                     // lo*hi
            load_b_frag(b, sm[3], n0, seg, lane);   // B lo
            load_a_frag(a, sm[0], m0, seg, lane);   // A hi
            mma_all(acc, a, b);                     // hi*lo
        }
    }

    const int rr = lane >> 2, cc = (lane & 3) * 2;
    #pragma unroll
    for (int mt = 0; mt < 4; mt++) {
        #pragma unroll
        for (int nt = 0; nt < 4; nt++) {
            const int r = m0 + mt * 16 + rr;
            const int c = n0 + nt * 8 + cc;
            *reinterpret_cast<float2*>(Cout + (size_t)r * ldc + c) =
                make_float2(acc[mt][nt][0], acc[mt][nt][1]);
            *reinterpret_cast<float2*>(Cout + (size_t)(r + 8) * ldc + c) =
                make_float2(acc[mt][nt][2], acc[mt][nt][3]);
        }
    }
}

// ---------------------------------------------------------------------------
// Kernel: scores = Q K^T (tensor cores). grid (4, 4, 256)
// ---------------------------------------------------------------------------
__global__ __launch_bounds__(256) void scores_mma()
{
    const int bh = blockIdx.z;
    const size_t rowBase = blockIdx.x * 128, colBase = blockIdx.y * 128;
    mma_gemm(g_Qh + ((size_t)bh * Nseq + rowBase) * D,
             g_Ql + ((size_t)bh * Nseq + rowBase) * D, D,
             g_Kh + ((size_t)bh * Nseq + colBase) * D,
             g_Kl + ((size_t)bh * Nseq + colBase) * D, D,
             D, g_S + (size_t)bh * Nseq * Nseq + rowBase * Nseq + colBase, Nseq);
}

// ---------------------------------------------------------------------------
// Kernel: A = P V (tensor cores, B = V^T). grid (4, 1, 256)
// ---------------------------------------------------------------------------
__global__ __launch_bounds__(256) void av_mma()
{
    const int bh = blockIdx.z, b = bh >> 2, h = bh & 3;
    const size_t rowBase = blockIdx.x * 128;
    mma_gemm(g_Ph + ((size_t)bh * Nseq + rowBase) * Nseq,
             g_Pl + ((size_t)bh * Nseq + rowBase) * Nseq, Nseq,
             g_Vth + (size_t)bh * E * Nseq,
             g_Vtl + (size_t)bh * E * Nseq, Nseq,
             Nseq, g_A + ((size_t)b * Nseq + rowBase) * (H * E) + (size_t)h * E, H * E);
}

// ======================= FFMA machinery (QKV / MLP) =======================
#define TSTRIDE 132
#define BUFSZ   (8 * TSTRIDE)

template<bool TRANSB>
__device__ __forceinline__ void gemm128(
    const float* __restrict__ Ag, int lda,
    const float* __restrict__ Bg, int ldb,
    int K, float* __restrict__ sm, float acc[8][8])
{
    float* As = sm;
    float* Bs = sm + 2 * BUFSZ;
    const int tid  = threadIdx.x;
    const int lane = tid & 31, w = tid >> 5;
    const int wm = w >> 2, wn = w & 3;
    const int rc = lane >> 2, cc = lane & 3;
    const int mA0 = wm * 64 + rc * 4;
    const int nB0 = wn * 32 + cc * 4;
    const int m_a = tid >> 1, k_a = (tid & 1) * 4;
    const int k_b = tid >> 5, n_b = (tid & 31) * 4;
    const int n_t = tid >> 1, k_t = (tid & 1) * 4;

    #pragma unroll
    for (int i = 0; i < 8; i++)
        #pragma unroll
        for (int j = 0; j < 8; j++) acc[i][j] = 0.f;

    const float* pA = Ag + (size_t)m_a * lda + k_a;
    const float* pB = TRANSB ? (Bg + (size_t)n_t * ldb + k_t)
                             : (Bg + (size_t)k_b * ldb + n_b);
    float4 aR = *reinterpret_cast<const float4*>(pA);
    float4 bR = *reinterpret_cast<const float4*>(pB);
    {
        float av[4] = {aR.x, aR.y, aR.z, aR.w};
        #pragma unroll
        for (int t = 0; t < 4; t++) As[(k_a + t) * TSTRIDE + m_a] = av[t];
        if (TRANSB) {
            float bv[4] = {bR.x, bR.y, bR.z, bR.w};
            #pragma unroll
            for (int t = 0; t < 4; t++) Bs[(k_t + t) * TSTRIDE + n_t] = bv[t];
        } else {
            *reinterpret_cast<float4*>(Bs + k_b * TSTRIDE + n_b) = bR;
        }
    }
    __syncthreads();

    const int NT = K >> 3;
    for (int it = 0; it < NT; it++) {
        const int cur = (it & 1) * BUFSZ, nxt = ((it + 1) & 1) * BUFSZ;
        if (it + 1 < NT) {
            const int kcc = (it + 1) * 8;
            aR = *reinterpret_cast<const float4*>(pA + kcc);
            bR = TRANSB ? *reinterpret_cast<const float4*>(pB + kcc)
                        : *reinterpret_cast<const float4*>(pB + (size_t)kcc * ldb);
        }
        const float* Ac = As + cur;
        const float* Bc = Bs + cur;
        #pragma unroll
        for (int k = 0; k < 8; k++) {
            const float* ar = Ac + k * TSTRIDE;
            const float* br = Bc + k * TSTRIDE;
            float4 a0 = *reinterpret_cast<const float4*>(ar + mA0);
            float4 a1 = *reinterpret_cast<const float4*>(ar + mA0 + 32);
            float4 b0 = *reinterpret_cast<const float4*>(br + nB0);
            float4 b1 = *reinterpret_cast<const float4*>(br + nB0 + 16);
            float a[8] = {a0.x,a0.y,a0.z,a0.w,a1.x,a1.y,a1.z,a1.w};
            float bb[8] = {b0.x,b0.y,b0.z,b0.w,b1.x,b1.y,b1.z,b1.w};
            #pragma unroll
            for (int i = 0; i < 8; i++)
                #pragma unroll
                for (int j = 0; j < 8; j++)
                    acc[i][j] += a[i] * bb[j];
        }
        if (it + 1 < NT) {
            float av[4] = {aR.x, aR.y, aR.z, aR.w};
            #pragma unroll
            for (int t = 0; t < 4; t++) As[nxt + (k_a + t) * TSTRIDE + m_a] = av[t];
            if (TRANSB) {
                float bv[4] = {bR.x, bR.y, bR.z, bR.w};
                #pragma unroll
                for (int t = 0; t < 4; t++) Bs[nxt + (k_t + t) * TSTRIDE + n_t] = bv[t];
            } else {
                *reinterpret_cast<float4*>(Bs + nxt + k_b * TSTRIDE + n_b) = bR;
            }
        }
        __syncthreads();
    }
}

__device__ __forceinline__ int acc_row(int i) {
    const int lane = threadIdx.x & 31, w = threadIdx.x >> 5;
    return (w >> 2) * 64 + ((i < 4) ? 0 : 32) + (lane >> 2) * 4 + (i & 3);
}
__device__ __forceinline__ int acc_col0() {
    const int lane = threadIdx.x & 31, w = threadIdx.x >> 5;
    return (w & 3) * 32 + (lane & 3) * 4;
}

__device__ __forceinline__ void ln_block(float acc[8][8], float* lnbuf)
{
    float* lnS = lnbuf;
    float* lnQ = lnbuf + 512;
    float* mrs = lnbuf + 1024;
    const int tid = threadIdx.x, lane = tid & 31, w = tid >> 5;
    const int wn = w & 3, cc = lane & 3;
    #pragma unroll
    for (int i = 0; i < 8; i++) {
        float s = 0.f, q = 0.f;
        #pragma unroll
        for (int j = 0; j < 8; j++) { float v = acc[i][j]; s += v; q += v * v; }
        s += __shfl_xor_sync(0xffffffffu, s, 1);
        s += __shfl_xor_sync(0xffffffffu, s, 2);
        q += __shfl_xor_sync(0xffffffffu, q, 1);
        q += __shfl_xor_sync(0xffffffffu, q, 2);
        if (cc == 0) {
            int row = acc_row(i);
            lnS[row * 4 + wn] = s;
            lnQ[row * 4 + wn] = q;
        }
    }
    __syncthreads();
    if (tid < 128) {
        float s = lnS[tid*4] + lnS[tid*4+1] + lnS[tid*4+2] + lnS[tid*4+3];
        float q = lnQ[tid*4] + lnQ[tid*4+1] + lnQ[tid*4+2] + lnQ[tid*4+3];
        float mean = s * (1.0f / 128.0f);
        float var  = q * (1.0f / 128.0f) - mean * mean;
        mrs[tid]       = mean;
        mrs[128 + tid] = rsqrtf(var + 1e-5f);
    }
    __syncthreads();
    #pragma unroll
    for (int i = 0; i < 8; i++) {
        int row = acc_row(i);
        float mu = mrs[row], rs = mrs[128 + row];
        #pragma unroll
        for (int j = 0; j < 8; j++) acc[i][j] = (acc[i][j] - mu) * rs;
    }
}

__device__ __forceinline__ void store_tile(const float acc[8][8],
                                           float* __restrict__ Cg, int ldc)
{
    const int c0 = acc_col0();
    #pragma unroll
    for (int i = 0; i < 8; i++) {
        int r = acc_row(i);
        float4 v0 = make_float4(acc[i][0], acc[i][1], acc[i][2], acc[i][3]);
        float4 v1 = make_float4(acc[i][4], acc[i][5], acc[i][6], acc[i][7]);
        float* p = Cg + (size_t)r * ldc + c0;
        *reinterpret_cast<float4*>(p)      = v0;
        *reinterpret_cast<float4*>(p + 16) = v1;
    }
}

__device__ __forceinline__ uint32_t pack_hi2(float v0, float v1, uint32_t& lo)
{
    __nv_bfloat16 h0 = __float2bfloat16(v0), h1 = __float2bfloat16(v1);
    __nv_bfloat16 l0 = __float2bfloat16(v0 - __bfloat162float(h0));
    __nv_bfloat16 l1 = __float2bfloat16(v1 - __bfloat162float(h1));
    lo = (uint32_t)__bfloat16_as_ushort(l0) | ((uint32_t)__bfloat16_as_ushort(l1) << 16);
    return (uint32_t)__bfloat16_as_ushort(h0) | ((uint32_t)__bfloat16_as_ushort(h1) << 16);
}

// ---------------------------------------------------------------------------
// Kernel 1: QKV projection + bias + LN -> bf16 hi/lo planes. grid (256, 4, 3)
// ---------------------------------------------------------------------------
__global__ __launch_bounds__(256, 2) void qkv_kernel(
    const float* __restrict__ x,
    const float* __restrict__ Wq, const float* __restrict__ bq,
    const float* __restrict__ Wk, const float* __restrict__ bk,
    const float* __restrict__ Wv, const float* __restrict__ bv)
{
    __shared__ float sm[4 * BUFSZ + 1280];
    const int rowBase = blockIdx.x * 128;
    const int h = blockIdx.y, which = blockIdx.z;

    const float* W; const float* bias;
    if      (which == 0) { W = Wq + (size_t)h * E * D; bias = bq + h * D; }
    else if (which == 1) { W = Wk + (size_t)h * E * D; bias = bk + h * D; }
    else                 { W = Wv + (size_t)h * E * E; bias = bv + h * E; }

    float acc[8][8];
    gemm128<false>(x + (size_t)rowBase * E, E, W, D, E, sm, acc);

    const int c0 = acc_col0();
    float4 bb0 = *reinterpret_cast<const float4*>(bias + c0);
    float4 bb1 = *reinterpret_cast<const float4*>(bias + c0 + 16);
    float bv8[8] = {bb0.x,bb0.y,bb0.z,bb0.w,bb1.x,bb1.y,bb1.z,bb1.w};
    #pragma unroll
    for (int i = 0; i < 8; i++)
        #pragma unroll
        for (int j = 0; j < 8; j++) acc[i][j] += bv8[j];

    ln_block(acc, sm + 4 * BUFSZ);

    const int b = rowBase >> 9;
    const int nBase = rowBase & 511;
    const int bh = b * H + h;
    __nv_bfloat16* oh = (which == 0 ? g_Qh : (which == 1 ? g_Kh : g_Vh));
    __nv_bfloat16* ol = (which == 0 ? g_Ql : (which == 1 ? g_Kl : g_Vl));
    const size_t rowOff = (size_t)bh * Nseq + nBase;

    #pragma unroll
    for (int i = 0; i < 8; i++) {
        int r = acc_row(i);
        __nv_bfloat16* ph = oh + (rowOff + r) * 128 + c0;
        __nv_bfloat16* pl = ol + (rowOff + r) * 128 + c0;
        #pragma unroll
        for (int g = 0; g < 2; g++) {
            uint32_t l0, l1;
            uint32_t h0 = pack_hi2(acc[i][g*4+0], acc[i][g*4+1], l0);
            uint32_t h1 = pack_hi2(acc[i][g*4+2], acc[i][g*4+3], l1);
            *reinterpret_cast<uint2*>(ph + g * 16) = make_uint2(h0, h1);
            *reinterpret_cast<uint2*>(pl + g * 16) = make_uint2(l0, l1);
        }
    }
}

// ---------------------------------------------------------------------------
// Kernel: V transpose [bh][n][e] -> [bh][e][n]. grid (256, 4, 16)
// ---------------------------------------------------------------------------
__global__ __launch_bounds__(256) void vtrans_kernel()
{
    __shared__ __nv_bfloat16 th[32][33], tl[32][33];
    const int bh = blockIdx.x, e0 = blockIdx.y * 32, n0 = blockIdx.z * 32;
    const int tid = threadIdx.x;
    const size_t inBase = ((size_t)bh * Nseq + n0) * E + e0;
    #pragma unroll
    for (int s = 0; s < 4; s++) {
        int idx = tid + s * 256;
        int r = idx >> 5, c = idx & 31;
        th[r][c] = g_Vh[inBase + (size_t)r * E + c];
        tl[r][c] = g_Vl[inBase + (size_t)r * E + c];
    }
    __syncthreads();
    const size_t outBase = ((size_t)bh * E + e0) * Nseq + n0;
    #pragma unroll
    for (int s = 0; s < 4; s++) {
        int idx = tid + s * 256;
        int r = idx >> 5, c = idx & 31;
        g_Vth[outBase + (size_t)r * Nseq + c] = th[c][r];
        g_Vtl[outBase + (size_t)r * Nseq + c] = tl[c][r];
    }
}

// ---------------------------------------------------------------------------
// Kernel: batch-axis softmax; emits P as bf16 hi/lo. grid (4096)
// ---------------------------------------------------------------------------
__global__ __launch_bounds__(256) void softmax_kernel()
{
    const size_t idx = (size_t)blockIdx.x * 256 + threadIdx.x;   // H*N*N
    const size_t stride = (size_t)H * Nseq * Nseq;
    float v[64];
    float mx = -1e30f;
    #pragma unroll
    for (int b = 0; b < 64; b++) {
        float t = g_S[(size_t)b * stride + idx] * (1.0f / 11.0f);
        v[b] = t;
        mx = fmaxf(mx, t);
    }
    float s = 0.f;
    #pragma unroll
    for (int b = 0; b < 64; b++) { float e = __expf(v[b] - mx); v[b] = e; s += e; }
    const float inv = 1.0f / s;
    #pragma unroll
    for (int b = 0; b < 64; b++) {
        float p = v[b] * inv;
        __nv_bfloat16 hp = __float2bfloat16(p);
        __nv_bfloat16 lp = __float2bfloat16(p - __bfloat162float(hp));
        g_Ph[(size_t)b * stride + idx] = hp;
        g_Pl[(size_t)b * stride + idx] = lp;
    }
}

// ---------------------------------------------------------------------------
// Kernel 5: h1 = relu(A_cat @ W1 + b1). grid (256)
// ---------------------------------------------------------------------------
__global__ __launch_bounds__(256, 2) void mlp1_kernel(
    const float* __restrict__ W1, const float* __restrict__ b1)
{
    __shared__ float sm[4 * BUFSZ];
    const int rowBase = blockIdx.x * 128;
    float acc[8][8];
    gemm128<false>(g_A + (size_t)rowBase * (H * E), H * E, W1, E, H * E, sm, acc);
    const int c0 = acc_col0();
    float4 bb0 = *reinterpret_cast<const float4*>(b1 + c0);
    float4 bb1 = *reinterpret_cast<const float4*>(b1 + c0 + 16);
    float bv8[8] = {bb0.x,bb0.y,bb0.z,bb0.w,bb1.x,bb1.y,bb1.z,bb1.w};
    #pragma unroll
    for (int i = 0; i < 8; i++)
        #pragma unroll
        for (int j = 0; j < 8; j++) acc[i][j] = fmaxf(acc[i][j] + bv8[j], 0.f);
    store_tile(acc, g_H1 + (size_t)rowBase * E, E);
}

// ---------------------------------------------------------------------------
// Kernel 6: out = LN(x + relu(h1 @ W2 + b2)) * gamma + beta. grid (256)
// ---------------------------------------------------------------------------
__global__ __launch_bounds__(256, 2) void mlp2_kernel(
    const float* __restrict__ x,
    const float* __restrict__ W2, const float* __restrict__ b2,
    const float* __restrict__ gamma, const float* __restrict__ beta,
    float* __restrict__ out)
{
    __shared__ float sm[4 * BUFSZ + 1280];
    const int rowBase = blockIdx.x * 128;
    float acc[8][8];
    gemm128<false>(g_H1 + (size_t)rowBase * E, E, W2, E, E, sm, acc);

    const int c0 = acc_col0();
    float4 bb0 = *reinterpret_cast<const float4*>(b2 + c0);
    float4 bb1 = *reinterpret_cast<const float4*>(b2 + c0 + 16);
    float bv8[8] = {bb0.x,bb0.y,bb0.z,bb0.w,bb1.x,bb1.y,bb1.z,bb1.w};
    #pragma unroll
    for (int i = 0; i < 8; i++) {
        int rg = rowBase + acc_row(i);
        float4 x0 = *reinterpret_cast<const float4*>(x + (size_t)rg * E + c0);
        float4 x1 = *reinterpret_cast<const float4*>(x + (size_t)rg * E + c0 + 16);
        float xv[8] = {x0.x,x0.y,x0.z,x0.w,x1.x,x1.y,x1.z,x1.w};
        #pragma unroll
        for (int j = 0; j < 8; j++)
            acc[i][j] = fmaxf(acc[i][j] + bv8[j], 0.f) + xv[j];
    }

    ln_block(acc, sm + 4 * BUFSZ);

    float4 g0 = *reinterpret_cast<const float4*>(gamma + c0);
    float4 g1 = *reinterpret_cast<const float4*>(gamma + c0 + 16);
    float4 e0 = *reinterpret_cast<const float4*>(beta + c0);
    float4 e1 = *reinterpret_cast<const float4*>(beta + c0 + 16);
    float gv[8] = {g0.x,g0.y,g0.z,g0.w,g1.x,g1.y,g1.z,g1.w};
    float ev[8] = {e0.x,e0.y,e0.z,e0.w,e1.x,e1.y,e1.z,e1.w};
    #pragma unroll
    for (int i = 0; i < 8; i++)
        #pragma unroll
        for (int j = 0; j < 8; j++) acc[i][j] = acc[i][j] * gv[j] + ev[j];

    store_tile(acc, out + (size_t)rowBase * E, E);
}

// ---------------------------------------------------------------------------
extern "C" void kernel_launch(void* const* d_in, const int* in_sizes, int n_in,
                              void* d_out, int out_size)
{
    const float* x     = (const float*)d_in[0];
    const float* Wq    = (const float*)d_in[1];
    const float* bq    = (const float*)d_in[2];
    const float* Wk    = (const float*)d_in[3];
    const float* bk    = (const float*)d_in[4];
    const float* Wv    = (const float*)d_in[5];
    const float* bv    = (const float*)d_in[6];
    const float* W1    = (const float*)d_in[7];
    const float* b1    = (const float*)d_in[8];
    const float* W2    = (const float*)d_in[9];
    const float* b2    = (const float*)d_in[10];
    const float* gamma = (const float*)d_in[11];
    const float* beta  = (const float*)d_in[12];
    float* out = (float*)d_out;

    dim3 blk(256);
    qkv_kernel    <<<dim3(256, 4, 3), blk>>>(x, Wq, bq, Wk, bk, Wv, bv);
    vtrans_kernel <<<dim3(256, 4, 16), blk>>>();
    scores_mma    <<<dim3(4, 4, 256), blk>>>();
    softmax_kernel<<<dim3(4096), blk>>>();
    av_mma        <<<dim3(4, 1, 256), blk>>>();
    mlp1_kernel   <<<dim3(256), blk>>>(W1, b1);
    mlp2_kernel   <<<dim3(256), blk>>>(x, W2, b2, gamma, beta, out);
}

// round 6
// speedup vs baseline: 2.9395x; 1.2940x over previous
#include <cuda_runtime.h>
#include <cuda_bf16.h>
#include <cstdint>

constexpr int Bdim = 64;
constexpr int Nseq = 512;
constexpr int E    = 128;
constexpr int D    = 128;
constexpr int H    = 4;

// ---------------- scratch (allocation-free) ----------------
__device__ __nv_bfloat16 g_xh [(size_t)Bdim*Nseq*E];
__device__ __nv_bfloat16 g_xl [(size_t)Bdim*Nseq*E];
__device__ __nv_bfloat16 g_WTh[12 * 128 * 128];          // [which*4+h][d][e]
__device__ __nv_bfloat16 g_WTl[12 * 128 * 128];
__device__ __nv_bfloat16 g_W1Th[128 * 512];              // [e_out][k]
__device__ __nv_bfloat16 g_W1Tl[128 * 512];
__device__ __nv_bfloat16 g_W2Th[128 * 128];
__device__ __nv_bfloat16 g_W2Tl[128 * 128];
__device__ __nv_bfloat16 g_Qh[(size_t)Bdim*H*Nseq*D];
__device__ __nv_bfloat16 g_Ql[(size_t)Bdim*H*Nseq*D];
__device__ __nv_bfloat16 g_Kh[(size_t)Bdim*H*Nseq*D];
__device__ __nv_bfloat16 g_Kl[(size_t)Bdim*H*Nseq*D];
__device__ __nv_bfloat16 g_Vh[(size_t)Bdim*H*Nseq*E];    // [bh][n][e]
__device__ __nv_bfloat16 g_Vl[(size_t)Bdim*H*Nseq*E];
__device__ __nv_bfloat16 g_Vth[(size_t)Bdim*H*E*Nseq];   // [bh][e][n]
__device__ __nv_bfloat16 g_Vtl[(size_t)Bdim*H*E*Nseq];
__device__ float         g_S [(size_t)Bdim*H*Nseq*Nseq]; // fp32 scores
__device__ __nv_bfloat16 g_Ph[(size_t)Bdim*H*Nseq*Nseq];
__device__ __nv_bfloat16 g_Pl[(size_t)Bdim*H*Nseq*Nseq];
__device__ __nv_bfloat16 g_Ah[(size_t)Bdim*Nseq*H*E];    // [B,N,512] concat
__device__ __nv_bfloat16 g_Al[(size_t)Bdim*Nseq*H*E];
__device__ __nv_bfloat16 g_H1h[(size_t)Bdim*Nseq*E];
__device__ __nv_bfloat16 g_H1l[(size_t)Bdim*Nseq*E];

// ======================= mma.sync machinery =======================
__device__ __forceinline__ void ldsm_x4(uint32_t r[4], const void* p) {
    uint32_t addr = (uint32_t)__cvta_generic_to_shared(p);
    asm volatile("ldmatrix.sync.aligned.m8n8.x4.shared.b16 {%0,%1,%2,%3}, [%4];"
                 : "=r"(r[0]), "=r"(r[1]), "=r"(r[2]), "=r"(r[3]) : "r"(addr));
}
__device__ __forceinline__ void mma16816(float c[4], const uint32_t a[4], const uint32_t b[2]) {
    asm volatile("mma.sync.aligned.m16n8k16.row.col.f32.bf16.bf16.f32 "
                 "{%0,%1,%2,%3}, {%4,%5,%6,%7}, {%8,%9}, {%0,%1,%2,%3};"
                 : "+f"(c[0]), "+f"(c[1]), "+f"(c[2]), "+f"(c[3])
                 : "r"(a[0]), "r"(a[1]), "r"(a[2]), "r"(a[3]), "r"(b[0]), "r"(b[1]));
}
// smem plane: 128 rows x 32 bf16 (64B rows), 16B chunks XOR-swizzled
__device__ __forceinline__ int sw_idx(int row, int seg) {
    return row * 32 + ((seg ^ ((row >> 1) & 3)) << 3);
}
__device__ __forceinline__ void cp_plane(__nv_bfloat16* dst, const __nv_bfloat16* src,
                                         int ld, int kc, int tid)
{
    #pragma unroll
    for (int s = 0; s < 2; s++) {
        int idx = tid + s * 256;
        int row = idx >> 2, seg = idx & 3;
        uint32_t d = (uint32_t)__cvta_generic_to_shared(dst + sw_idx(row, seg));
        const __nv_bfloat16* g = src + (size_t)row * ld + kc + seg * 8;
        asm volatile("cp.async.cg.shared.global [%0], [%1], 16;" :: "r"(d), "l"(g));
    }
}
__device__ __forceinline__ void load_a_frag(uint32_t a[4][4], const __nv_bfloat16* plane,
                                            int m0, int seg_base, int lane)
{
    const int r = lane & 15, half = lane >> 4;
    #pragma unroll
    for (int t = 0; t < 4; t++)
        ldsm_x4(a[t], plane + sw_idx(m0 + t * 16 + r, seg_base + half));
}
__device__ __forceinline__ void load_b_frag(uint32_t b[4][2], const __nv_bfloat16* plane,
                                            int n0, int seg_base, int lane)
{
    const int r = lane & 15, half = lane >> 4;
    #pragma unroll
    for (int p = 0; p < 2; p++) {
        uint32_t t[4];
        ldsm_x4(t, plane + sw_idx(n0 + p * 16 + r, seg_base + half));
        b[2*p][0]   = t[0];
        b[2*p+1][0] = t[1];
        b[2*p][1]   = t[2];
        b[2*p+1][1] = t[3];
    }
}
__device__ __forceinline__ void mma_all(float acc[4][4][4], const uint32_t a[4][4],
                                        const uint32_t b[4][2])
{
    #pragma unroll
    for (int mt = 0; mt < 4; mt++)
        #pragma unroll
        for (int nt = 0; nt < 4; nt++)
            mma16816(acc[mt][nt], a[mt], b[nt]);
}

// ---------------------------------------------------------------------------
// Split-bf16 (3-product) 128x128 GEMM core with cp.async double buffering.
// sm: 2 stages x 4 planes x 4096 bf16 = 64KB dynamic smem.
// ---------------------------------------------------------------------------
__device__ void mma_core(const __nv_bfloat16* __restrict__ Ah,
                         const __nv_bfloat16* __restrict__ Al, int lda,
                         const __nv_bfloat16* __restrict__ Bh,
                         const __nv_bfloat16* __restrict__ Bl, int ldb,
                         int K, __nv_bfloat16* sm, float acc[4][4][4])
{
    const int tid = threadIdx.x, lane = tid & 31, wid = tid >> 5;
    const int m0 = (wid >> 2) * 64, n0 = (wid & 3) * 32;

    #pragma unroll
    for (int mt = 0; mt < 4; mt++)
        #pragma unroll
        for (int nt = 0; nt < 4; nt++)
            #pragma unroll
            for (int q = 0; q < 4; q++) acc[mt][nt][q] = 0.f;

    cp_plane(sm + 0*4096, Ah, lda, 0, tid);
    cp_plane(sm + 1*4096, Al, lda, 0, tid);
    cp_plane(sm + 2*4096, Bh, ldb, 0, tid);
    cp_plane(sm + 3*4096, Bl, ldb, 0, tid);
    asm volatile("cp.async.commit_group;");

    const int NC = K >> 5;
    for (int c = 0; c < NC; c++) {
        __nv_bfloat16* st = sm + (c & 1) * 16384;
        if (c + 1 < NC) {
            __nv_bfloat16* st2 = sm + ((c + 1) & 1) * 16384;
            const int kc = (c + 1) * 32;
            cp_plane(st2 + 0*4096, Ah, lda, kc, tid);
            cp_plane(st2 + 1*4096, Al, lda, kc, tid);
            cp_plane(st2 + 2*4096, Bh, ldb, kc, tid);
            cp_plane(st2 + 3*4096, Bl, ldb, kc, tid);
            asm volatile("cp.async.commit_group;");
            asm volatile("cp.async.wait_group 1;");
        } else {
            asm volatile("cp.async.wait_group 0;");
        }
        __syncthreads();
        #pragma unroll
        for (int ks = 0; ks < 2; ks++) {
            const int seg = ks * 2;
            uint32_t a[4][4];
            uint32_t b[4][2];
            load_b_frag(b, st + 2*4096, n0, seg, lane);   // B hi
            load_a_frag(a, st + 0*4096, m0, seg, lane);   // A hi
            mma_all(acc, a, b);                           // hi*hi
            load_a_frag(a, st + 1*4096, m0, seg, lane);   // A lo
            mma_all(acc, a, b);                           // lo*hi
            load_b_frag(b, st + 3*4096, n0, seg, lane);   // B lo
            load_a_frag(a, st + 0*4096, m0, seg, lane);   // A hi
            mma_all(acc, a, b);                           // hi*lo
        }
        __syncthreads();
    }
}

// LayerNorm over 128 cols, operating on the mma fragment layout.
// lnbuf >= 1280 floats (reuses gemm smem).
__device__ void ln_mma(float acc[4][4][4], float* lnbuf)
{
    float* lnS = lnbuf;
    float* lnQ = lnbuf + 512;
    float* mrs = lnbuf + 1024;
    const int tid = threadIdx.x, lane = tid & 31, wid = tid >> 5;
    const int wn = wid & 3, m0 = (wid >> 2) * 64;
    const int rr = lane >> 2, cg = lane & 3;

    #pragma unroll
    for (int mt = 0; mt < 4; mt++)
        #pragma unroll
        for (int half = 0; half < 2; half++) {
            float s = 0.f, q = 0.f;
            #pragma unroll
            for (int nt = 0; nt < 4; nt++) {
                float v0 = acc[mt][nt][2*half], v1 = acc[mt][nt][2*half+1];
                s += v0 + v1; q += v0 * v0 + v1 * v1;
            }
            s += __shfl_xor_sync(0xffffffffu, s, 1);
            s += __shfl_xor_sync(0xffffffffu, s, 2);
            q += __shfl_xor_sync(0xffffffffu, q, 1);
            q += __shfl_xor_sync(0xffffffffu, q, 2);
            if (cg == 0) {
                int row = m0 + mt * 16 + half * 8 + rr;
                lnS[row * 4 + wn] = s;
                lnQ[row * 4 + wn] = q;
            }
        }
    __syncthreads();
    if (tid < 128) {
        float s = lnS[tid*4] + lnS[tid*4+1] + lnS[tid*4+2] + lnS[tid*4+3];
        float q = lnQ[tid*4] + lnQ[tid*4+1] + lnQ[tid*4+2] + lnQ[tid*4+3];
        float mean = s * (1.0f / 128.0f);
        float var  = q * (1.0f / 128.0f) - mean * mean;
        mrs[tid]       = mean;
        mrs[128 + tid] = rsqrtf(var + 1e-5f);
    }
    __syncthreads();
    #pragma unroll
    for (int mt = 0; mt < 4; mt++)
        #pragma unroll
        for (int half = 0; half < 2; half++) {
            int row = m0 + mt * 16 + half * 8 + rr;
            float mu = mrs[row], rs = mrs[128 + row];
            #pragma unroll
            for (int nt = 0; nt < 4; nt++) {
                acc[mt][nt][2*half]   = (acc[mt][nt][2*half]   - mu) * rs;
                acc[mt][nt][2*half+1] = (acc[mt][nt][2*half+1] - mu) * rs;
            }
        }
}

__device__ __forceinline__ uint32_t pack_hi2(float v0, float v1, uint32_t& lo)
{
    __nv_bfloat16 h0 = __float2bfloat16(v0), h1 = __float2bfloat16(v1);
    __nv_bfloat16 l0 = __float2bfloat16(v0 - __bfloat162float(h0));
    __nv_bfloat16 l1 = __float2bfloat16(v1 - __bfloat162float(h1));
    lo = (uint32_t)__bfloat16_as_ushort(l0) | ((uint32_t)__bfloat16_as_ushort(l1) << 16);
    return (uint32_t)__bfloat16_as_ushort(h0) | ((uint32_t)__bfloat16_as_ushort(h1) << 16);
}

// store acc as hi/lo bf16 planes. rows offset into oh/ol with leading dim ldc.
__device__ __forceinline__ void store_hilo(const float acc[4][4][4],
                                           __nv_bfloat16* oh, __nv_bfloat16* ol,
                                           int ldc)
{
    const int lane = threadIdx.x & 31, wid = threadIdx.x >> 5;
    const int m0 = (wid >> 2) * 64, n0 = (wid & 3) * 32;
    const int rr = lane >> 2, cg = lane & 3;
    #pragma unroll
    for (int mt = 0; mt < 4; mt++)
        #pragma unroll
        for (int half = 0; half < 2; half++) {
            int row = m0 + mt * 16 + half * 8 + rr;
            #pragma unroll
            for (int nt = 0; nt < 4; nt++) {
                int c = n0 + nt * 8 + 2 * cg;
                uint32_t lo;
                uint32_t hi = pack_hi2(acc[mt][nt][2*half], acc[mt][nt][2*half+1], lo);
                *reinterpret_cast<uint32_t*>(oh + (size_t)row * ldc + c) = hi;
                *reinterpret_cast<uint32_t*>(ol + (size_t)row * ldc + c) = lo;
            }
        }
}

// ======================= prep kernels =======================
__global__ __launch_bounds__(256) void split_x_kernel(const float* __restrict__ x)
{
    const size_t i4 = (size_t)blockIdx.x * 256 + threadIdx.x;
    float4 v = *reinterpret_cast<const float4*>(x + i4 * 4);
    uint32_t l0, l1;
    uint32_t h0 = pack_hi2(v.x, v.y, l0);
    uint32_t h1 = pack_hi2(v.z, v.w, l1);
    *reinterpret_cast<uint2*>(g_xh + i4 * 4) = make_uint2(h0, h1);
    *reinterpret_cast<uint2*>(g_xl + i4 * 4) = make_uint2(l0, l1);
}

// transpose+split a [R,C] fp32 matrix -> dst hi/lo [C,R] bf16
__device__ __forceinline__ void transplit_tile(const float* src, __nv_bfloat16* dh,
                                               __nv_bfloat16* dl, int R, int C,
                                               int r0, int c0)
{
    __shared__ float t[32][33];
    const int tid = threadIdx.x;
    #pragma unroll
    for (int s = 0; s < 4; s++) {
        int idx = tid + s * 256;
        int r = idx >> 5, c = idx & 31;
        t[r][c] = src[(size_t)(r0 + r) * C + c0 + c];
    }
    __syncthreads();
    #pragma unroll
    for (int s = 0; s < 4; s++) {
        int idx = tid + s * 256;
        int co = idx >> 5, ro = idx & 31;
        float v = t[ro][co];
        __nv_bfloat16 h = __float2bfloat16(v);
        dh[(size_t)(c0 + co) * R + r0 + ro] = h;
        dl[(size_t)(c0 + co) * R + r0 + ro] = __float2bfloat16(v - __bfloat162float(h));
    }
}

__global__ __launch_bounds__(256) void qkv_prep_kernel(
    const float* __restrict__ Wq, const float* __restrict__ Wk, const float* __restrict__ Wv)
{
    const int midx = blockIdx.x;           // which*4 + h
    const int which = midx >> 2, h = midx & 3;
    const float* src = (which == 0 ? Wq : (which == 1 ? Wk : Wv)) + (size_t)h * 128 * 128;
    transplit_tile(src, g_WTh + (size_t)midx * 16384, g_WTl + (size_t)midx * 16384,
                   128, 128, blockIdx.y * 32, blockIdx.z * 32);
}
__global__ __launch_bounds__(256) void w1_prep_kernel(const float* __restrict__ W1)
{
    transplit_tile(W1, g_W1Th, g_W1Tl, 512, 128, blockIdx.x * 32, blockIdx.y * 32);
}
__global__ __launch_bounds__(256) void w2_prep_kernel(const float* __restrict__ W2)
{
    transplit_tile(W2, g_W2Th, g_W2Tl, 128, 128, blockIdx.x * 32, blockIdx.y * 32);
}

// ======================= main kernels =======================
extern __shared__ __nv_bfloat16 dynsm[];

// QKV: grid (256, H, 3)
__global__ __launch_bounds__(256) void qkv_mma(
    const float* __restrict__ bq, const float* __restrict__ bk, const float* __restrict__ bv)
{
    const int rowBase = blockIdx.x * 128;
    const int h = blockIdx.y, which = blockIdx.z;
    const int midx = which * 4 + h;
    const float* bias = (which == 0 ? bq : (which == 1 ? bk : bv)) + (size_t)h * 128;

    float acc[4][4][4];
    mma_core(g_xh + (size_t)rowBase * E, g_xl + (size_t)rowBase * E, E,
             g_WTh + (size_t)midx * 16384, g_WTl + (size_t)midx * 16384, E,
             E, dynsm, acc);

    const int lane = threadIdx.x & 31, wid = threadIdx.x >> 5;
    const int n0 = (wid & 3) * 32, cg = lane & 3;
    #pragma unroll
    for (int nt = 0; nt < 4; nt++) {
        float2 bv2 = *reinterpret_cast<const float2*>(bias + n0 + nt * 8 + 2 * cg);
        #pragma unroll
        for (int mt = 0; mt < 4; mt++) {
            acc[mt][nt][0] += bv2.x; acc[mt][nt][1] += bv2.y;
            acc[mt][nt][2] += bv2.x; acc[mt][nt][3] += bv2.y;
        }
    }
    ln_mma(acc, (float*)dynsm);

    const int b = rowBase >> 9, nBase = rowBase & 511;
    const int bh = b * H + h;
    const size_t off = ((size_t)bh * Nseq + nBase) * 128;
    __nv_bfloat16* oh = (which == 0 ? g_Qh : (which == 1 ? g_Kh : g_Vh)) + off;
    __nv_bfloat16* ol = (which == 0 ? g_Ql : (which == 1 ? g_Kl : g_Vl)) + off;
    store_hilo(acc, oh, ol, 128);
}

// V transpose: grid (256, 4, 16)
__global__ __launch_bounds__(256) void vtrans_kernel()
{
    __shared__ __nv_bfloat16 th[32][33], tl[32][33];
    const int bh = blockIdx.x, e0 = blockIdx.y * 32, n0 = blockIdx.z * 32;
    const int tid = threadIdx.x;
    const size_t inBase = ((size_t)bh * Nseq + n0) * E + e0;
    #pragma unroll
    for (int s = 0; s < 4; s++) {
        int idx = tid + s * 256;
        int r = idx >> 5, c = idx & 31;
        th[r][c] = g_Vh[inBase + (size_t)r * E + c];
        tl[r][c] = g_Vl[inBase + (size_t)r * E + c];
    }
    __syncthreads();
    const size_t outBase = ((size_t)bh * E + e0) * Nseq + n0;
    #pragma unroll
    for (int s = 0; s < 4; s++) {
        int idx = tid + s * 256;
        int r = idx >> 5, c = idx & 31;
        g_Vth[outBase + (size_t)r * Nseq + c] = th[c][r];
        g_Vtl[outBase + (size_t)r * Nseq + c] = tl[c][r];
    }
}

// scores = Q K^T -> fp32 S. grid (4, 4, 256)
__global__ __launch_bounds__(256) void scores_mma()
{
    const int bh = blockIdx.z;
    const size_t rowBase = blockIdx.x * 128, colBase = blockIdx.y * 128;
    float acc[4][4][4];
    mma_core(g_Qh + ((size_t)bh * Nseq + rowBase) * D,
             g_Ql + ((size_t)bh * Nseq + rowBase) * D, D,
             g_Kh + ((size_t)bh * Nseq + colBase) * D,
             g_Kl + ((size_t)bh * Nseq + colBase) * D, D, D, dynsm, acc);

    float* Cout = g_S + (size_t)bh * Nseq * Nseq + rowBase * Nseq + colBase;
    const int lane = threadIdx.x & 31, wid = threadIdx.x >> 5;
    const int m0 = (wid >> 2) * 64, n0 = (wid & 3) * 32;
    const int rr = lane >> 2, cg = lane & 3;
    #pragma unroll
    for (int mt = 0; mt < 4; mt++)
        #pragma unroll
        for (int half = 0; half < 2; half++) {
            int r = m0 + mt * 16 + half * 8 + rr;
            #pragma unroll
            for (int nt = 0; nt < 4; nt++) {
                int c = n0 + nt * 8 + 2 * cg;
                *reinterpret_cast<float2*>(Cout + (size_t)r * Nseq + c) =
                    make_float2(acc[mt][nt][2*half], acc[mt][nt][2*half+1]);
            }
        }
}

// batch-axis softmax. grid (4096)
__global__ __launch_bounds__(256) void softmax_kernel()
{
    const size_t idx = (size_t)blockIdx.x * 256 + threadIdx.x;
    const size_t stride = (size_t)H * Nseq * Nseq;
    float v[64];
    float mx = -1e30f;
    #pragma unroll
    for (int b = 0; b < 64; b++) {
        float t = g_S[(size_t)b * stride + idx] * (1.0f / 11.0f);
        v[b] = t;
        mx = fmaxf(mx, t);
    }
    float s = 0.f;
    #pragma unroll
    for (int b = 0; b < 64; b++) { float e = __expf(v[b] - mx); v[b] = e; s += e; }
    const float inv = 1.0f / s;
    #pragma unroll
    for (int b = 0; b < 64; b++) {
        float p = v[b] * inv;
        __nv_bfloat16 hp = __float2bfloat16(p);
        __nv_bfloat16 lp = __float2bfloat16(p - __bfloat162float(hp));
        g_Ph[(size_t)b * stride + idx] = hp;
        g_Pl[(size_t)b * stride + idx] = lp;
    }
}

// A = P V -> hi/lo concat layout. grid (4, 1, 256)
__global__ __launch_bounds__(256) void av_mma()
{
    const int bh = blockIdx.z, b = bh >> 2, h = bh & 3;
    const size_t rowBase = blockIdx.x * 128;
    float acc[4][4][4];
    mma_core(g_Ph + ((size_t)bh * Nseq + rowBase) * Nseq,
             g_Pl + ((size_t)bh * Nseq + rowBase) * Nseq, Nseq,
             g_Vth + (size_t)bh * E * Nseq,
             g_Vtl + (size_t)bh * E * Nseq, Nseq, Nseq, dynsm, acc);
    const size_t off = ((size_t)b * Nseq + rowBase) * (H * E) + (size_t)h * E;
    store_hilo(acc, g_Ah + off, g_Al + off, H * E);
}

// h1 = relu(A @ W1 + b1) -> hi/lo. grid (256)
__global__ __launch_bounds__(256) void mlp1_mma(const float* __restrict__ b1)
{
    const int rowBase = blockIdx.x * 128;
    float acc[4][4][4];
    mma_core(g_Ah + (size_t)rowBase * (H * E), g_Al + (size_t)rowBase * (H * E), H * E,
             g_W1Th, g_W1Tl, H * E, H * E, dynsm, acc);

    const int lane = threadIdx.x & 31, wid = threadIdx.x >> 5;
    const int n0 = (wid & 3) * 32, cg = lane & 3;
    #pragma unroll
    for (int nt = 0; nt < 4; nt++) {
        float2 bv2 = *reinterpret_cast<const float2*>(b1 + n0 + nt * 8 + 2 * cg);
        #pragma unroll
        for (int mt = 0; mt < 4; mt++) {
            acc[mt][nt][0] = fmaxf(acc[mt][nt][0] + bv2.x, 0.f);
            acc[mt][nt][1] = fmaxf(acc[mt][nt][1] + bv2.y, 0.f);
            acc[mt][nt][2] = fmaxf(acc[mt][nt][2] + bv2.x, 0.f);
            acc[mt][nt][3] = fmaxf(acc[mt][nt][3] + bv2.y, 0.f);
        }
    }
    store_hilo(acc, g_H1h + (size_t)rowBase * E, g_H1l + (size_t)rowBase * E, E);
}

// out = LN(x + relu(h1 @ W2 + b2)) * gamma + beta. grid (256)
__global__ __launch_bounds__(256) void mlp2_mma(
    const float* __restrict__ x, const float* __restrict__ b2,
    const float* __restrict__ gamma, const float* __restrict__ beta,
    float* __restrict__ out)
{
    const int rowBase = blockIdx.x * 128;
    float acc[4][4][4];
    mma_core(g_H1h + (size_t)rowBase * E, g_H1l + (size_t)rowBase * E, E,
             g_W2Th, g_W2Tl, E, E, dynsm, acc);

    const int lane = threadIdx.x & 31, wid = threadIdx.x >> 5;
    const int m0 = (wid >> 2) * 64, n0 = (wid & 3) * 32;
    const int rr = lane >> 2, cg = lane & 3;
    #pragma unroll
    for (int nt = 0; nt < 4; nt++) {
        const int c = n0 + nt * 8 + 2 * cg;
        float2 bv2 = *reinterpret_cast<const float2*>(b2 + c);
        #pragma unroll
        for (int mt = 0; mt < 4; mt++)
            #pragma unroll
            for (int half = 0; half < 2; half++) {
                int row = rowBase + m0 + mt * 16 + half * 8 + rr;
                float2 xv = *reinterpret_cast<const float2*>(x + (size_t)row * E + c);
                acc[mt][nt][2*half]   = fmaxf(acc[mt][nt][2*half]   + bv2.x, 0.f) + xv.x;
                acc[mt][nt][2*half+1] = fmaxf(acc[mt][nt][2*half+1] + bv2.y, 0.f) + xv.y;
            }
    }

    ln_mma(acc, (float*)dynsm);

    #pragma unroll
    for (int nt = 0; nt < 4; nt++) {
        const int c = n0 + nt * 8 + 2 * cg;
        float2 gv = *reinterpret_cast<const float2*>(gamma + c);
        float2 ev = *reinterpret_cast<const float2*>(beta + c);
        #pragma unroll
        for (int mt = 0; mt < 4; mt++)
            #pragma unroll
            for (int half = 0; half < 2; half++) {
                int row = rowBase + m0 + mt * 16 + half * 8 + rr;
                float o0 = acc[mt][nt][2*half]   * gv.x + ev.x;
                float o1 = acc[mt][nt][2*half+1] * gv.y + ev.y;
                *reinterpret_cast<float2*>(out + (size_t)row * E + c) = make_float2(o0, o1);
            }
    }
}

// ---------------------------------------------------------------------------
extern "C" void kernel_launch(void* const* d_in, const int* in_sizes, int n_in,
                              void* d_out, int out_size)
{
    const float* x     = (const float*)d_in[0];
    const float* Wq    = (const float*)d_in[1];
    const float* bq    = (const float*)d_in[2];
    const float* Wk    = (const float*)d_in[3];
    const float* bk    = (const float*)d_in[4];
    const float* Wv    = (const float*)d_in[5];
    const float* bv    = (const float*)d_in[6];
    const float* W1    = (const float*)d_in[7];
    const float* b1    = (const float*)d_in[8];
    const float* W2    = (const float*)d_in[9];
    const float* b2    = (const float*)d_in[10];
    const float* gamma = (const float*)d_in[11];
    const float* beta  = (const float*)d_in[12];
    float* out = (float*)d_out;

    const int SMEM = 2 * 4 * 4096 * (int)sizeof(__nv_bfloat16);   // 64KB
    // Unconditional (idempotent, host-side, capture-safe) — no static guards.
    cudaFuncSetAttribute(qkv_mma,    cudaFuncAttributeMaxDynamicSharedMemorySize, SMEM);
    cudaFuncSetAttribute(scores_mma, cudaFuncAttributeMaxDynamicSharedMemorySize, SMEM);
    cudaFuncSetAttribute(av_mma,     cudaFuncAttributeMaxDynamicSharedMemorySize, SMEM);
    cudaFuncSetAttribute(mlp1_mma,   cudaFuncAttributeMaxDynamicSharedMemorySize, SMEM);
    cudaFuncSetAttribute(mlp2_mma,   cudaFuncAttributeMaxDynamicSharedMemorySize, SMEM);

    dim3 blk(256);
    split_x_kernel <<<dim3(4096), blk>>>(x);
    qkv_prep_kernel<<<dim3(12, 4, 4), blk>>>(Wq, Wk, Wv);
    w1_prep_kernel <<<dim3(16, 4), blk>>>(W1);
    w2_prep_kernel <<<dim3(4, 4), blk>>>(W2);
    qkv_mma        <<<dim3(256, 4, 3), blk, SMEM>>>(bq, bk, bv);
    vtrans_kernel  <<<dim3(256, 4, 16), blk>>>();
    scores_mma     <<<dim3(4, 4, 256), blk, SMEM>>>();
    softmax_kernel <<<dim3(4096), blk>>>();
    av_mma         <<<dim3(4, 1, 256), blk, SMEM>>>();
    mlp1_mma       <<<dim3(256), blk, SMEM>>>(b1);
    mlp2_mma       <<<dim3(256), blk, SMEM>>>(x, b2, gamma, beta, out);
}